// round 6
// baseline (speedup 1.0000x reference)
#include <cuda_runtime.h>
#include <math.h>
#include <stdint.h>

#define BB 8
#define NN 128
#define CC 128

// ---- scratch (no allocations allowed) ----
__device__ float g_ep[BB*NN*NN];
__device__ float g_vpA[BB*NN*CC];
__device__ float g_vpB[BB*NN*CC];
__device__ float g_q[BB*NN*CC];
__device__ float g_k[BB*NN*CC];
__device__ float g_attn[BB*NN*NN];

__device__ __forceinline__ float lrelu(float x) { return x >= 0.f ? x : 0.01f * x; }

#define BN_SCALE 0.9999950000374997f

__device__ __forceinline__ float blockReduceSum(float v, float* red) {
    int tid = threadIdx.x;
    int nw = blockDim.x >> 5;
    #pragma unroll
    for (int off = 16; off; off >>= 1) v += __shfl_down_sync(0xffffffffu, v, off);
    if ((tid & 31) == 0) red[tid >> 5] = v;
    __syncthreads();
    float s = (tid < nw) ? red[tid] : 0.f;
    if (tid < 32) {
        #pragma unroll
        for (int off = 16; off; off >>= 1) s += __shfl_down_sync(0xffffffffu, s, off);
        if (tid == 0) red[0] = s;
    }
    __syncthreads();
    float r = red[0];
    __syncthreads();
    return r;
}

__device__ __forceinline__ float blockReduceMax(float v, float* red) {
    int tid = threadIdx.x;
    int nw = blockDim.x >> 5;
    #pragma unroll
    for (int off = 16; off; off >>= 1) v = fmaxf(v, __shfl_down_sync(0xffffffffu, v, off));
    if ((tid & 31) == 0) red[tid >> 5] = v;
    __syncthreads();
    float s = (tid < nw) ? red[tid] : -1e30f;
    if (tid < 32) {
        #pragma unroll
        for (int off = 16; off; off >>= 1) s = fmaxf(s, __shfl_down_sync(0xffffffffu, s, off));
        if (tid == 0) red[0] = s;
    }
    __syncthreads();
    float r = red[0];
    __syncthreads();
    return r;
}

// ---- TF32 mma helpers ----
__device__ __forceinline__ uint32_t f2tf(float x) {
    uint32_t r; asm("cvt.rna.tf32.f32 %0, %1;" : "=r"(r) : "f"(x)); return r;
}
__device__ __forceinline__ void mma_tf32(float* d,
    uint32_t a0, uint32_t a1, uint32_t a2, uint32_t a3,
    uint32_t b0, uint32_t b1)
{
    asm volatile("mma.sync.aligned.m16n8k8.row.col.f32.tf32.tf32.f32 "
        "{%0,%1,%2,%3}, {%4,%5,%6,%7}, {%8,%9}, {%0,%1,%2,%3};"
        : "+f"(d[0]), "+f"(d[1]), "+f"(d[2]), "+f"(d[3])
        : "r"(a0), "r"(a1), "r"(a2), "r"(a3), "r"(b0), "r"(b1));
}

#define SPAD 132
#define HPAD 264
#define WPAD 136

// ============================================================================
// psim (tensor-core version): fused sim -> MLP(tf32 split mma) -> sigmoid ->
// topk -> l1norm -> renorm, per (b,i). 256 threads, grid = B*N.
// ============================================================================
__global__ __launch_bounds__(256, 1)
void psim_tc_kernel(const float* __restrict__ vp, const float* __restrict__ ep_in,
                    float* __restrict__ ep_out,
                    const float* __restrict__ w1, const float* __restrict__ w2,
                    const float* __restrict__ w3, const float* __restrict__ b3,
                    int kval)
{
    extern __shared__ float sm[];
    float* S   = sm;                    // [128][SPAD] sim (fp32), later H2
    float* H1  = S + 128 * SPAD;        // [128][HPAD] fp32
    float* WS  = H1 + 128 * HPAD;       // [2][8][WPAD] weight stage
    float* vpi = WS + 2 * 8 * WPAD;     // [128]
    float* w3s = vpi + 128;             // [128]
    float* ev  = w3s + 128;             // [128]
    float* red = ev + 128;              // [32]

    const int tid = threadIdx.x;
    const int b = blockIdx.x >> 7;
    const int i = blockIdx.x & 127;
    const float* vpb = vp + b * NN * CC;

    const int warp = tid >> 5, lane = tid & 31;
    const int gid = lane >> 2, tg = lane & 3;
    const int wm = warp >> 1, wn = warp & 1;   // 4 M-tiles x 2 N-tiles
    const int jbase = wm * 32;

    if (tid < 128) { vpi[tid] = vpb[i * CC + tid]; w3s[tid] = w3[tid]; }
    __syncthreads();

    // sim row-major: S[j][c] = (vp[i,c]-vp[j,c])^2
    for (int idx = tid; idx < 128 * 128; idx += 256) {
        int j = idx >> 7, c = idx & 127;
        float d = vpi[c] - vpb[idx];
        S[j * SPAD + c] = d * d;
    }
    __syncthreads();

    float acc[2][8][4];

    // ---------------- GEMM1: H1 = lrelu(bn(S @ w1)), N=256 in two halves ----
    for (int half = 0; half < 2; ++half) {
        #pragma unroll
        for (int mf = 0; mf < 2; ++mf)
            #pragma unroll
            for (int nf = 0; nf < 8; ++nf)
                #pragma unroll
                for (int q = 0; q < 4; ++q) acc[mf][nf][q] = 0.f;

        // stage chunk 0
        for (int t = tid; t < 8 * 128; t += 256) {
            int k = t >> 7, o = t & 127;
            WS[k * WPAD + o] = w1[k * 256 + half * 128 + o];
        }
        __syncthreads();

        for (int s = 0; s < 16; ++s) {
            int buf = s & 1;
            if (s + 1 < 16) {
                int k0n = (s + 1) * 8;
                for (int t = tid; t < 8 * 128; t += 256) {
                    int k = t >> 7, o = t & 127;
                    WS[(1 - buf) * 8 * WPAD + k * WPAD + o] =
                        w1[(k0n + k) * 256 + half * 128 + o];
                }
            }
            const int k0 = s * 8;
            uint32_t Ah[2][4], Al[2][4];
            #pragma unroll
            for (int mf = 0; mf < 2; ++mf) {
                int r = jbase + mf * 16 + gid;
                float a0 = S[r * SPAD + k0 + tg];
                float a1 = S[(r + 8) * SPAD + k0 + tg];
                float a2 = S[r * SPAD + k0 + tg + 4];
                float a3 = S[(r + 8) * SPAD + k0 + tg + 4];
                Ah[mf][0] = f2tf(a0); Al[mf][0] = __float_as_uint(a0 - __uint_as_float(Ah[mf][0]));
                Ah[mf][1] = f2tf(a1); Al[mf][1] = __float_as_uint(a1 - __uint_as_float(Ah[mf][1]));
                Ah[mf][2] = f2tf(a2); Al[mf][2] = __float_as_uint(a2 - __uint_as_float(Ah[mf][2]));
                Ah[mf][3] = f2tf(a3); Al[mf][3] = __float_as_uint(a3 - __uint_as_float(Ah[mf][3]));
            }
            const float* Wb = WS + buf * 8 * WPAD;
            #pragma unroll
            for (int nf = 0; nf < 8; ++nf) {
                int o = wn * 64 + nf * 8 + gid;
                float b0f = Wb[tg * WPAD + o];
                float b1f = Wb[(tg + 4) * WPAD + o];
                uint32_t Bh0 = f2tf(b0f), Bl0 = __float_as_uint(b0f - __uint_as_float(Bh0));
                uint32_t Bh1 = f2tf(b1f), Bl1 = __float_as_uint(b1f - __uint_as_float(Bh1));
                #pragma unroll
                for (int mf = 0; mf < 2; ++mf) {
                    mma_tf32(acc[mf][nf], Ah[mf][0], Ah[mf][1], Ah[mf][2], Ah[mf][3], Bh0, Bh1);
                    mma_tf32(acc[mf][nf], Ah[mf][0], Ah[mf][1], Ah[mf][2], Ah[mf][3], Bl0, Bl1);
                    mma_tf32(acc[mf][nf], Al[mf][0], Al[mf][1], Al[mf][2], Al[mf][3], Bh0, Bh1);
                }
            }
            __syncthreads();
        }

        // epilogue: lrelu(bn()) -> H1 half
        #pragma unroll
        for (int mf = 0; mf < 2; ++mf) {
            int r = jbase + mf * 16 + gid;
            #pragma unroll
            for (int nf = 0; nf < 8; ++nf) {
                int o = half * 128 + wn * 64 + nf * 8 + 2 * tg;
                H1[r * HPAD + o]         = lrelu(acc[mf][nf][0] * BN_SCALE);
                H1[r * HPAD + o + 1]     = lrelu(acc[mf][nf][1] * BN_SCALE);
                H1[(r + 8) * HPAD + o]     = lrelu(acc[mf][nf][2] * BN_SCALE);
                H1[(r + 8) * HPAD + o + 1] = lrelu(acc[mf][nf][3] * BN_SCALE);
            }
        }
        __syncthreads();
    }

    // ---------------- GEMM2: H2 = lrelu(bn(H1 @ w2)), K=256, N=128 ---------
    #pragma unroll
    for (int mf = 0; mf < 2; ++mf)
        #pragma unroll
        for (int nf = 0; nf < 8; ++nf)
            #pragma unroll
            for (int q = 0; q < 4; ++q) acc[mf][nf][q] = 0.f;

    for (int t = tid; t < 8 * 128; t += 256) {
        int k = t >> 7, o = t & 127;
        WS[k * WPAD + o] = w2[k * 128 + o];
    }
    __syncthreads();

    for (int s = 0; s < 32; ++s) {
        int buf = s & 1;
        if (s + 1 < 32) {
            int k0n = (s + 1) * 8;
            for (int t = tid; t < 8 * 128; t += 256) {
                int k = t >> 7, o = t & 127;
                WS[(1 - buf) * 8 * WPAD + k * WPAD + o] = w2[(k0n + k) * 128 + o];
            }
        }
        const int k0 = s * 8;
        uint32_t Ah[2][4], Al[2][4];
        #pragma unroll
        for (int mf = 0; mf < 2; ++mf) {
            int r = jbase + mf * 16 + gid;
            float a0 = H1[r * HPAD + k0 + tg];
            float a1 = H1[(r + 8) * HPAD + k0 + tg];
            float a2 = H1[r * HPAD + k0 + tg + 4];
            float a3 = H1[(r + 8) * HPAD + k0 + tg + 4];
            Ah[mf][0] = f2tf(a0); Al[mf][0] = __float_as_uint(a0 - __uint_as_float(Ah[mf][0]));
            Ah[mf][1] = f2tf(a1); Al[mf][1] = __float_as_uint(a1 - __uint_as_float(Ah[mf][1]));
            Ah[mf][2] = f2tf(a2); Al[mf][2] = __float_as_uint(a2 - __uint_as_float(Ah[mf][2]));
            Ah[mf][3] = f2tf(a3); Al[mf][3] = __float_as_uint(a3 - __uint_as_float(Ah[mf][3]));
        }
        const float* Wb = WS + buf * 8 * WPAD;
        #pragma unroll
        for (int nf = 0; nf < 8; ++nf) {
            int o = wn * 64 + nf * 8 + gid;
            float b0f = Wb[tg * WPAD + o];
            float b1f = Wb[(tg + 4) * WPAD + o];
            uint32_t Bh0 = f2tf(b0f), Bl0 = __float_as_uint(b0f - __uint_as_float(Bh0));
            uint32_t Bh1 = f2tf(b1f), Bl1 = __float_as_uint(b1f - __uint_as_float(Bh1));
            #pragma unroll
            for (int mf = 0; mf < 2; ++mf) {
                mma_tf32(acc[mf][nf], Ah[mf][0], Ah[mf][1], Ah[mf][2], Ah[mf][3], Bh0, Bh1);
                mma_tf32(acc[mf][nf], Ah[mf][0], Ah[mf][1], Ah[mf][2], Ah[mf][3], Bl0, Bl1);
                mma_tf32(acc[mf][nf], Al[mf][0], Al[mf][1], Al[mf][2], Al[mf][3], Bh0, Bh1);
            }
        }
        __syncthreads();
    }

    // H2 -> S region
    #pragma unroll
    for (int mf = 0; mf < 2; ++mf) {
        int r = jbase + mf * 16 + gid;
        #pragma unroll
        for (int nf = 0; nf < 8; ++nf) {
            int o = wn * 64 + nf * 8 + 2 * tg;
            S[r * SPAD + o]         = lrelu(acc[mf][nf][0] * BN_SCALE);
            S[r * SPAD + o + 1]     = lrelu(acc[mf][nf][1] * BN_SCALE);
            S[(r + 8) * SPAD + o]     = lrelu(acc[mf][nf][2] * BN_SCALE);
            S[(r + 8) * SPAD + o + 1] = lrelu(acc[mf][nf][3] * BN_SCALE);
        }
    }
    __syncthreads();

    // ---- e_j = sigmoid(H2[j] . w3 + b3) ----
    float e = 0.f;
    if (tid < NN) {
        const float* h2row = S + tid * SPAD;
        #pragma unroll 4
        for (int o = 0; o < 128; ++o) e += h2row[o] * w3s[o];
        e += b3[0];
        e = 1.f / (1.f + expf(-e));
    }

    // ---- postprocess row with ep ----
    float eplv = 0.f;
    if (tid < NN) {
        float epv = ep_in[(b * NN + i) * NN + tid];
        eplv = (tid == i) ? 0.f : epv;
    }
    float em = e * eplv;
    if (tid < NN) ev[tid] = em;
    float ep_sum = blockReduceSum(eplv, red);   // also orders ev[] writes

    if (kval > 0 && kval < NN) {
        int cnt = 0;
        float mine = 0.f;
        if (tid < NN) {
            mine = ev[tid];
            for (int j = 0; j < NN; ++j) {
                float o = ev[j];
                cnt += (o > mine) || (o == mine && j < tid);
            }
        }
        if (tid < NN && cnt >= kval) em = 0.f;
    }

    float s = blockReduceSum(fabsf(em), red);
    float scale = ep_sum / fmaxf(s, 1e-12f);
    float val = 0.f;
    if (tid < NN) val = em * scale + ((tid == i) ? 1.f : 0.f) + 1e-6f;
    float rowsum = blockReduceSum(val, red);
    if (tid < NN) ep_out[(b * NN + i) * NN + tid] = val / rowsum;
}

// ============================================================================
// q/k projection
// ============================================================================
__global__ void proj_kernel(const float* __restrict__ vp, const float* __restrict__ wq,
                            const float* __restrict__ wk,
                            float* __restrict__ q, float* __restrict__ k)
{
    __shared__ float row[128];
    int tid = threadIdx.x;
    int bn = blockIdx.x;
    if (tid < 128) row[tid] = vp[bn * CC + tid];
    __syncthreads();
    int o = tid & 127;
    const float* w = (tid < 128) ? wq : wk;
    float acc = 0.f;
    #pragma unroll 4
    for (int c = 0; c < 128; ++c) acc += row[c] * w[c * 128 + o];
    if (tid < 128) q[bn * 128 + o] = acc;
    else           k[bn * 128 + o] = acc;
}

// ============================================================================
// mha
// ============================================================================
__global__ void mha_kernel(const float* __restrict__ q, const float* __restrict__ k,
                           float* __restrict__ attn)
{
    extern __shared__ float sm[];
    float* kb   = sm;               // [128][129]
    float* qrow = kb + 128 * 129;   // [128]
    float* red  = qrow + 128;       // [32]
    int tid = threadIdx.x;          // 128
    int b = blockIdx.x >> 7, i = blockIdx.x & 127;
    const float* ksrc = k + b * NN * CC;
    for (int idx = tid; idx < NN * CC; idx += 128) {
        int j = idx >> 7, c = idx & 127;
        kb[j * 129 + c] = ksrc[idx];
    }
    qrow[tid] = q[(b * NN + i) * CC + tid];
    __syncthreads();

    const float isd = 0.17677669529663687f; // 1/sqrt(32)
    float out = 0.f;
    for (int h = 0; h < 4; ++h) {
        float l = 0.f;
        const float* kr = kb + tid * 129 + h * 32;
        const float* qr = qrow + h * 32;
        #pragma unroll
        for (int d = 0; d < 32; ++d) l += qr[d] * kr[d];
        l *= isd;
        float mx = blockReduceMax(l, red);
        float ex = expf(l - mx);
        float ssum = blockReduceSum(ex, red);
        out += ex / ssum;
    }
    attn[(b * NN + i) * NN + tid] = out * 0.25f;
}

// ============================================================================
// d2p
// ============================================================================
__global__ void d2p_kernel(const float* __restrict__ ep, const float* __restrict__ attn,
                           const float* __restrict__ vp, float* __restrict__ vp_out,
                           const float* __restrict__ w1, const float* __restrict__ w2)
{
    __shared__ float edge[128];
    __shared__ float nf[256];
    __shared__ float h[256];
    __shared__ float red[32];
    int tid = threadIdx.x;  // 256
    int b = blockIdx.x >> 7, i = blockIdx.x & 127;
    const float* vpb = vp + b * NN * CC;

    float wv = 0.f;
    if (tid < 128) {
        wv = ep[(b * NN + i) * NN + tid] * attn[(b * NN + i) * NN + tid];
        if (tid == i) wv = 0.f;
    }
    float s = blockReduceSum(fabsf(wv), red);
    float inv = 1.f / fmaxf(s, 1e-12f);
    if (tid < 128) { edge[tid] = wv * inv; nf[tid] = vpb[i * CC + tid]; }
    __syncthreads();
    if (tid >= 128) {
        int c = tid - 128;
        float a = 0.f;
        #pragma unroll 4
        for (int j = 0; j < 128; ++j) a += edge[j] * vpb[j * CC + c];
        nf[128 + c] = a;
    }
    __syncthreads();
    {
        float acc = 0.f;
        #pragma unroll 4
        for (int kk = 0; kk < 256; ++kk) acc += nf[kk] * w1[kk * 256 + tid];
        h[tid] = lrelu(acc * BN_SCALE);
    }
    __syncthreads();
    if (tid < 128) {
        float acc = 0.f;
        #pragma unroll 4
        for (int kk = 0; kk < 256; ++kk) acc += h[kk] * w2[kk * 128 + tid];
        vp_out[(b * NN + i) * CC + tid] = lrelu(acc * BN_SCALE);
    }
}

// ============================================================================
extern "C" void kernel_launch(void* const* d_in, const int* in_sizes, int n_in,
                              void* d_out, int out_size)
{
    const float* vp      = (const float*)d_in[0];
    const float* ep0     = (const float*)d_in[1];
    const float* pre_w1  = (const float*)d_in[2];
    const float* pre_w2  = (const float*)d_in[3];
    const float* pre_w3  = (const float*)d_in[4];
    const float* pre_b3  = (const float*)d_in[5];
    const float* ps_w1   = (const float*)d_in[6];
    const float* ps_w2   = (const float*)d_in[7];
    const float* ps_w3   = (const float*)d_in[8];
    const float* ps_b3   = (const float*)d_in[9];
    const float* d2pw1   = (const float*)d_in[10];
    const float* d2pw2   = (const float*)d_in[11];
    const float* mha_wq  = (const float*)d_in[12];
    const float* mha_wk  = (const float*)d_in[13];
    float* out = (float*)d_out;

    float *ep, *vpA, *vpB, *qb, *kb, *at;
    cudaGetSymbolAddress((void**)&ep,  g_ep);
    cudaGetSymbolAddress((void**)&vpA, g_vpA);
    cudaGetSymbolAddress((void**)&vpB, g_vpB);
    cudaGetSymbolAddress((void**)&qb,  g_q);
    cudaGetSymbolAddress((void**)&kb,  g_k);
    cudaGetSymbolAddress((void**)&at,  g_attn);

    const int psim_smem = (128 * SPAD + 128 * HPAD + 2 * 8 * WPAD + 3 * 128 + 32) * (int)sizeof(float);
    cudaFuncSetAttribute(psim_tc_kernel, cudaFuncAttributeMaxDynamicSharedMemorySize, psim_smem);
    const int mha_smem = (128 * 129 + 128 + 32) * (int)sizeof(float);
    cudaFuncSetAttribute(mha_kernel, cudaFuncAttributeMaxDynamicSharedMemorySize, mha_smem);

    dim3 grid(BB * NN);

    psim_tc_kernel<<<grid, 256, psim_smem>>>(vp, ep0, ep, pre_w1, pre_w2, pre_w3, pre_b3, -1);

    const float* vcur = vp;
    float* vbuf[2] = {vpA, vpB};
    for (int g = 0; g < 2; ++g) {
        proj_kernel<<<grid, 256>>>(vcur, mha_wq + g * 128 * 128, mha_wk + g * 128 * 128, qb, kb);
        mha_kernel<<<grid, 128, mha_smem>>>(qb, kb, at);
        d2p_kernel<<<grid, 256>>>(ep, at, vcur, vbuf[g],
                                  d2pw1 + g * 256 * 256, d2pw2 + g * 256 * 128);
        int kv = (g == 0) ? 115 : 102;  // int(128*(1-0.1*(g+1)))
        float* epo = (g == 1) ? out : ep;
        psim_tc_kernel<<<grid, 256, psim_smem>>>(vbuf[g], ep, epo,
                                                 ps_w1 + g * 128 * 256, ps_w2 + g * 256 * 128,
                                                 ps_w3 + g * 128, ps_b3 + g, kv);
        vcur = vbuf[g];
    }
}